// round 11
// baseline (speedup 1.0000x reference)
#include <cuda_runtime.h>
#include <cuda_bf16.h>

#define BB      32
#define SS      64
#define DD      8
#define NEIDX   512
#define NBINS2  (NEIDX * 2)    // (eidx, c0-half) bins
#define EMAX    150000
#define NW      5              // warps per CTA in fused kernel (160 threads)
#define CPB     16             // batch rows per CTA
#define NBC     128            // binning CTAs

// ---------------- device scratch ----------------
__device__ int g_part[NBC][NBINS2];
__device__ int g_base[NBC][NBINS2];
__device__ int g_bin_start[NBINS2 + 1];
__device__ int g_sorted[EMAX];           // packed: c0 | (c1<<5)

// ---------------- K1: per-CTA histogram over 1024 bins ----------------
__global__ __launch_bounds__(512) void k_hist(const int4* __restrict__ inc, int E) {
    __shared__ int sh[NBINS2];
    int tid = threadIdx.x;
    for (int t = tid; t < NBINS2; t += 512) sh[t] = 0;
    __syncthreads();
    int per = (E + NBC - 1) / NBC;
    int beg = blockIdx.x * per;
    int end = min(beg + per, E);
    for (int i = beg + tid; i < end; i += 512) {
        int4 r = inc[i];
        atomicAdd(&sh[(r.z * DD + r.w) * 2 + (r.x >> 4)], 1);
    }
    __syncthreads();
    for (int t = tid; t < NBINS2; t += 512) g_part[blockIdx.x][t] = sh[t];
}

// ---------------- K2: scan over 1024 bins (1 CTA, 1024 threads) -----------
__global__ __launch_bounds__(NBINS2) void k_scan() {
    __shared__ int s[NBINS2];
    int t = threadIdx.x;
    int run = 0;
    #pragma unroll 8
    for (int c = 0; c < NBC; c++) {
        int v = g_part[c][t];
        g_base[c][t] = run;
        run += v;
    }
    s[t] = run;
    __syncthreads();
    for (int off = 1; off < NBINS2; off <<= 1) {
        int x = (t >= off) ? s[t - off] : 0;
        __syncthreads();
        s[t] += x;
        __syncthreads();
    }
    g_bin_start[t + 1] = s[t];
    if (t == 0) g_bin_start[0] = 0;
}

// ---------------- K3: scatter (smem cursors) ----------------
__global__ __launch_bounds__(512) void k_scatter(const int4* __restrict__ inc, int E) {
    __shared__ int sc[NBINS2];
    int tid = threadIdx.x;
    for (int t = tid; t < NBINS2; t += 512)
        sc[t] = g_bin_start[t] + g_base[blockIdx.x][t];
    __syncthreads();
    int per = (E + NBC - 1) / NBC;
    int beg = blockIdx.x * per;
    int end = min(beg + per, E);
    for (int i = beg + tid; i < end; i += 512) {
        int4 r = inc[i];
        int b = (r.z * DD + r.w) * 2 + (r.x >> 4);
        int pos = atomicAdd(&sc[b], 1);
        g_sorted[pos] = r.x | (r.y << 5);
    }
}

// ---------------- K4: fused edge MLP + segment mean + output MLP ----------------
// Grid = 1024: CTA (e, half) owns c0 in [half*16, half*16+16). ~146 edges/CTA,
// NW=5 warps -> most warps do ONE 32-edge pass (edge-per-lane, 32 independent
// gathers). In-CTA 16-bucket counting sort by c0; reduce via stride-33 stage +
// shfl keys + register accumulate, flush on c0 change.
__global__ __launch_bounds__(NW * 32) void k_fused(
    const float* __restrict__ nodes,
    const float* __restrict__ W0,  const float* __restrict__ b0,
    const float* __restrict__ W1,  const float* __restrict__ b1,
    const float* __restrict__ oW0, const float* __restrict__ ob0,
    const float* __restrict__ oW1, const float* __restrict__ ob1,
    float* __restrict__ out)
{
    __shared__ __align__(16) float sW0[512];              // in_core0 [o][i] 32x16
    __shared__ __align__(16) float sW1[1024];             // in_core1 [o][i] 32x32
    __shared__ __align__(16) float s_stage[NW * 33 * 32]; // staging; reused in epilogue
    __shared__ __align__(16) float s_acc[CPB * 32];       // [c0loc][o]; reused as hh
    __shared__ int   s_srt[512];
    __shared__ int   s_hist[16], s_cur[16];
    __shared__ float sb0[32], sb1[32], s_ob0[32], s_ob1[16];

    int bx   = blockIdx.x;
    int e    = bx >> 1;
    int c0b  = (bx & 1) * CPB;
    int tid  = threadIdx.x;
    int warp = tid >> 5, lane = tid & 31;
    int c2   = e >> 3;

    for (int t = tid; t < 512;  t += NW * 32) sW0[t] = W0[e * 512 + t];
    for (int t = tid; t < 1024; t += NW * 32) sW1[t] = W1[e * 1024 + t];
    if (tid < 32) { sb0[tid] = b0[e * 32 + tid]; sb1[tid] = b1[e * 32 + tid]; }
    if (tid < 16) s_hist[tid] = 0;
    for (int t = tid; t < CPB * 32; t += NW * 32) s_acc[t] = 0.f;
    __syncthreads();

    // ---- in-CTA counting sort by c0 (16 buckets) ----
    int start = g_bin_start[bx];
    int n     = g_bin_start[bx + 1] - start;

    for (int i = tid; i < n; i += NW * 32)
        atomicAdd(&s_hist[g_sorted[start + i] & 15], 1);
    __syncthreads();
    if (warp == 0) {
        int v = (lane < 16) ? s_hist[lane] : 0;
        int x = v;
        #pragma unroll
        for (int off = 1; off < 16; off <<= 1) {
            int y = __shfl_up_sync(0xffffffffu, x, off);
            if (lane >= off) x += y;
        }
        if (lane < 16) s_cur[lane] = x - v;
    }
    __syncthreads();
    for (int i = tid; i < n; i += NW * 32) {
        int p = g_sorted[start + i];
        int pos = atomicAdd(&s_cur[p & 15], 1);
        s_srt[pos] = p;
    }
    __syncthreads();

    // ---- mainloop (most warps: exactly one pass) ----
    float* ST = s_stage + warp * 33 * 32;
    float racc = 0.f;
    int   rcur = -1;

    for (int j0 = warp * 32; j0 < n; j0 += NW * 32) {
        int j = j0 + lane;
        bool v = (j < n);
        int pk = v ? s_srt[j] : -1;
        int c1 = (pk >> 5) & 1023;
        const float4* xp = (const float4*)(nodes + (v ? (c1 * SS + c2) * 16 : 0));
        float4 x0 = xp[0], x1 = xp[1], x2 = xp[2], x3 = xp[3];

        // layer 1: h[o] per lane-edge; weights broadcast from SMEM
        float h[32];
        #pragma unroll
        for (int o = 0; o < 32; o++) {
            const float4* w = (const float4*)(sW0 + o * 16);
            float4 w0 = w[0], w1 = w[1], w2 = w[2], w3 = w[3];
            float s = sb0[o];
            s = fmaf(w0.x, x0.x, s); s = fmaf(w0.y, x0.y, s);
            s = fmaf(w0.z, x0.z, s); s = fmaf(w0.w, x0.w, s);
            s = fmaf(w1.x, x1.x, s); s = fmaf(w1.y, x1.y, s);
            s = fmaf(w1.z, x1.z, s); s = fmaf(w1.w, x1.w, s);
            s = fmaf(w2.x, x2.x, s); s = fmaf(w2.y, x2.y, s);
            s = fmaf(w2.z, x2.z, s); s = fmaf(w2.w, x2.w, s);
            s = fmaf(w3.x, x3.x, s); s = fmaf(w3.y, x3.y, s);
            s = fmaf(w3.z, x3.z, s); s = fmaf(w3.w, x3.w, s);
            h[o] = fmaxf(s, 0.f);
        }

        // layer 2: stage relu(g) at stride 33 (conflict-free)
        #pragma unroll 8
        for (int o = 0; o < 32; o++) {
            const float4* w = (const float4*)(sW1 + o * 32);
            float s = sb1[o];
            #pragma unroll
            for (int q = 0; q < 8; q++) {
                float4 ww = w[q];
                s = fmaf(ww.x, h[q * 4 + 0], s);
                s = fmaf(ww.y, h[q * 4 + 1], s);
                s = fmaf(ww.z, h[q * 4 + 2], s);
                s = fmaf(ww.w, h[q * 4 + 3], s);
            }
            ST[lane * 33 + o] = v ? fmaxf(s, 0.f) : 0.f;
        }
        __syncwarp();

        // transposed reduce: lane = o; flush only on c0 change (sorted)
        #pragma unroll
        for (int j2 = 0; j2 < 32; j2++) {
            int pk2 = __shfl_sync(0xffffffffu, pk, j2);
            if (pk2 >= 0) {
                int cl = pk2 & 15;
                if (cl != rcur) {
                    if (rcur >= 0) atomicAdd(&s_acc[rcur * 32 + lane], racc);
                    racc = 0.f;
                    rcur = cl;
                }
                racc += ST[j2 * 33 + lane];
            }
        }
        __syncwarp();
    }
    if (rcur >= 0) atomicAdd(&s_acc[rcur * 32 + lane], racc);
    __syncthreads();

    // ---- epilogue: reuse s_stage ----
    float* s_w0t = s_stage;              // 1024 floats
    float* s_w1t = s_stage + 1024;       // 512
    float* s_ef  = s_stage + 1536;       // 512

    for (int t = tid; t < 1024; t += NW * 32) {
        int o = t >> 5, i = t & 31;
        s_w0t[i * 32 + o] = oW0[e * 1024 + t];
    }
    for (int t = tid; t < 512; t += NW * 32) {
        int o = t >> 5, i = t & 31;
        s_w1t[i * 16 + o] = oW1[e * 512 + t];
    }
    if (tid < 32) s_ob0[tid] = ob0[e * 32 + tid];
    if (tid < 16) s_ob1[tid] = ob1[e * 16 + tid];

    for (int t = tid; t < CPB * 32; t += NW * 32) {
        int bl = t >> 5;
        int c = s_hist[bl];
        s_ef[t] = (c > 0) ? s_acc[t] / (float)c : 0.f;
    }
    __syncthreads();

    // out layer 1 (hh reuses s_acc)
    for (int t = tid; t < CPB * 32; t += NW * 32) {
        int bl = t >> 5, o = t & 31;
        float s = s_ob0[o];
        #pragma unroll
        for (int i = 0; i < 32; i++)
            s = fmaf(s_w0t[i * 32 + o], s_ef[bl * 32 + i], s);
        s_acc[t] = fmaxf(s, 0.f);
    }
    __syncthreads();

    // out layer 2 + store
    for (int t = tid; t < CPB * 16; t += NW * 32) {
        int bl = t >> 4, o = t & 15;
        float s = s_ob1[o];
        #pragma unroll
        for (int i = 0; i < 32; i++)
            s = fmaf(s_w1t[i * 16 + o], s_acc[bl * 32 + i], s);
        out[((c0b + bl) * NEIDX + e) * 16 + o] = fmaxf(s, 0.f);
    }
}

// ---------------- launch ----------------
extern "C" void kernel_launch(void* const* d_in, const int* in_sizes, int n_in,
                              void* d_out, int out_size) {
    const float* nodes = (const float*)d_in[0];
    const float* ic0   = (const float*)d_in[1];
    const float* ib0   = (const float*)d_in[2];
    const float* ic1   = (const float*)d_in[3];
    const float* ib1   = (const float*)d_in[4];
    const float* oc0   = (const float*)d_in[5];
    const float* ob0   = (const float*)d_in[6];
    const float* oc1   = (const float*)d_in[7];
    const float* ob1   = (const float*)d_in[8];
    const int4*  inc   = (const int4*)d_in[9];
    int E = in_sizes[9] / 4;
    float* out = (float*)d_out;

    k_hist<<<NBC, 512>>>(inc, E);
    k_scan<<<1, NBINS2>>>();
    k_scatter<<<NBC, 512>>>(inc, E);
    k_fused<<<NBINS2, NW * 32>>>(nodes, ic0, ib0, ic1, ib1,
                                 oc0, ob0, oc1, ob1, out);
}